// round 8
// baseline (speedup 1.0000x reference)
#include <cuda_runtime.h>

// LinearSpline: per-channel slope-clipped linear spline activation, fused.
// x: [32, 64, 128, 128] f32, coefficients_vect: [64*51] f32, scaling: [64] f32.
//
// Grid 8192, 256 threads, 4 float4/thread FRONT-BATCHED (launch_bounds minor
// occupancy target relaxed so ptxas keeps all 4 LDG.128 in flight).
// Channel constant per block; warp-0 shfl scan rebuilds the 50-entry
// {value, slope} table in smem once per block.

#define NCH   64
#define SZ    51
#define HALFI 25                               // SIZE // 2
#define GRID_D   (2.0 * 1.0 / (SZ - 1))        // 0.04 (double, matches python)
#define GRID_F   ((float)GRID_D)
#define TLO   (-25.0f)                         // clamp in t = xs*25 domain
#define THI   ( 24.0f)

#define THREADS   256
#define V4_PER_T  4
#define V4_PER_B  (THREADS * V4_PER_T)         // 1024 float4 = 4096 elems per block

__global__ void __launch_bounds__(THREADS, 4)   // allow up to 64 regs
spline_fused_kernel(const float4* __restrict__ x,
                    const float*  __restrict__ coeff,
                    const float*  __restrict__ scale,
                    float4* __restrict__ out) {
    __shared__ float2 tab[SZ - 1];             // {c0, slope} per interval
    __shared__ float  sh_s[2];                 // {s*25, 1/s}

    // block covers 4096 elems; plane = 16384; c = (b>>2) & 63
    int c = (blockIdx.x >> 2) & (NCH - 1);

    // ---- table build: warp 0, shfl parallel scan ---------------------------
    if (threadIdx.x < 32) {
        int lane = threadIdx.x;
        const float* cs = coeff + c * SZ;
        float a  = (2 * lane     <= 50) ? __ldg(cs + 2 * lane)     : 0.0f; // cs[2l]
        float bb = (2 * lane + 1 <= 50) ? __ldg(cs + 2 * lane + 1) : 0.0f; // cs[2l+1]
        float a_next = __shfl_down_sync(0xffffffff, a, 1);                 // cs[2l+2]
        float s_even = fminf(fmaxf(bb - a,      0.0f), GRID_F);  // slope[2l]
        float s_odd  = fminf(fmaxf(a_next - bb, 0.0f), GRID_F);  // slope[2l+1]
        float p = (lane <= 24) ? (s_even + s_odd) : 0.0f;
        float P = p;                                             // inclusive scan
#pragma unroll
        for (int off = 1; off < 32; off <<= 1) {
            float t = __shfl_up_sync(0xffffffff, P, off);
            if (lane >= off) P += t;
        }
        float v_even = P - p;                  // vals[2l]  (exclusive)
        float v_odd  = v_even + s_even;        // vals[2l+1]
        float mid = __shfl_sync(0xffffffff, v_odd, 12);   // vals[25]
        if (lane <= 24) {
            tab[2 * lane]     = make_float2(v_even - mid, s_even);
            tab[2 * lane + 1] = make_float2(v_odd  - mid, s_odd);
        }
        if (lane == 0) {
            float s = __ldg(scale + c);
            sh_s[0] = s * 25.0f;               // fold 1/GRID into the scale
            sh_s[1] = __fdividef(1.0f, s);
        }
    }
    __syncthreads();

    float s25   = sh_s[0];
    float inv_s = sh_s[1];
    int base = blockIdx.x * V4_PER_B + threadIdx.x;

    // Front-batch: 4 independent LDG.128 in flight per thread.
    float4 vin[V4_PER_T];
#pragma unroll
    for (int u = 0; u < V4_PER_T; ++u)
        vin[u] = __ldcs(x + base + u * THREADS);

#pragma unroll
    for (int u = 0; u < V4_PER_T; ++u) {
        float xin[4] = {vin[u].x, vin[u].y, vin[u].z, vin[u].w};
        float r[4];
#pragma unroll
        for (int k = 0; k < 4; ++k) {
            float t  = xin[k] * s25;                       // = xs / GRID
            float tc = fminf(fmaxf(t, TLO), THI);          // clamp in t-domain
            float fl = floorf(tc);                         // [-25, 24]
            float fr = t - fl;                             // frac from UNCLAMPED t
            int idx  = HALFI + (int)fl;                    // [0, 49]
            float2 p = tab[idx];                           // LDS.64 gather
            r[k] = fmaf(fr, p.y, p.x) * inv_s;
        }
        __stcs(out + base + u * THREADS, make_float4(r[0], r[1], r[2], r[3]));
    }
}

extern "C" void kernel_launch(void* const* d_in, const int* in_sizes, int n_in,
                              void* d_out, int out_size) {
    const float* x     = (const float*)d_in[0];
    const float* coeff = (const float*)d_in[1];
    const float* scl   = (const float*)d_in[2];
    float* out = (float*)d_out;

    int n  = out_size;                 // 33554432
    int blocks = n / (V4_PER_B * 4);   // 8192
    spline_fused_kernel<<<blocks, THREADS>>>((const float4*)x, coeff, scl,
                                             (float4*)out);
}

// round 9
// speedup vs baseline: 1.0498x; 1.0498x over previous
#include <cuda_runtime.h>

// LinearSpline: per-channel slope-clipped linear spline activation, fused.
// x: [32, 64, 128, 128] f32, coefficients_vect: [64*51] f32, scaling: [64] f32.
//
// R7-proven shape: grid 4096 (half (n,c) plane per block), 256 threads,
// 4 iterations x 2 front-batched float4/thread, regs<=32, occ ~82%.
// R8-validated t-domain math: t = x * (s*25); clamp/floor/frac in t-space.

#define NCH   64
#define SZ    51
#define HALFI 25                               // SIZE // 2
#define GRID_D   (2.0 * 1.0 / (SZ - 1))        // 0.04 (double, matches python)
#define GRID_F   ((float)GRID_D)
#define TLO   (-25.0f)                         // clamp bounds in t = xs*25 domain
#define THI   ( 24.0f)

#define THREADS   256
#define BLOCK_V4  2048                         // half-plane: 8192 elems / 4
#define ITERS     (BLOCK_V4 / (THREADS * 2))   // 4 iterations of 2 float4/thread

__global__ void __launch_bounds__(THREADS)
spline_fused_kernel(const float4* __restrict__ x,
                    const float*  __restrict__ coeff,
                    const float*  __restrict__ scale,
                    float4* __restrict__ out) {
    __shared__ float2 tab[SZ - 1];             // {c0, slope} per interval
    __shared__ float  sh_s[2];                 // {s*25, 1/s}

    // block's first element = b*8192 ; plane = 16384 elems ; c = (b>>1) & 63
    int c = (blockIdx.x >> 1) & (NCH - 1);

    // ---- table build, once per block: warp 0, shfl parallel scan ----------
    if (threadIdx.x < 32) {
        int lane = threadIdx.x;
        const float* cs = coeff + c * SZ;
        float a  = (2 * lane     <= 50) ? __ldg(cs + 2 * lane)     : 0.0f; // cs[2l]
        float bb = (2 * lane + 1 <= 50) ? __ldg(cs + 2 * lane + 1) : 0.0f; // cs[2l+1]
        float a_next = __shfl_down_sync(0xffffffff, a, 1);                 // cs[2l+2]
        float s_even = fminf(fmaxf(bb - a,      0.0f), GRID_F);  // slope[2l]
        float s_odd  = fminf(fmaxf(a_next - bb, 0.0f), GRID_F);  // slope[2l+1]
        float p = (lane <= 24) ? (s_even + s_odd) : 0.0f;
        float P = p;                                             // inclusive scan
#pragma unroll
        for (int off = 1; off < 32; off <<= 1) {
            float t = __shfl_up_sync(0xffffffff, P, off);
            if (lane >= off) P += t;
        }
        float v_even = P - p;                  // vals[2l]  (exclusive)
        float v_odd  = v_even + s_even;        // vals[2l+1]
        float mid = __shfl_sync(0xffffffff, v_odd, 12);   // vals[25]
        if (lane <= 24) {
            tab[2 * lane]     = make_float2(v_even - mid, s_even);
            tab[2 * lane + 1] = make_float2(v_odd  - mid, s_odd);
        }
        if (lane == 0) {
            float s = __ldg(scale + c);
            sh_s[0] = s * 25.0f;               // fold 1/GRID into the scale
            sh_s[1] = __fdividef(1.0f, s);
        }
    }
    __syncthreads();

    float s25   = sh_s[0];
    float inv_s = sh_s[1];
    int base = blockIdx.x * BLOCK_V4 + threadIdx.x;

#pragma unroll 2
    for (int it = 0; it < ITERS; ++it) {
        int o = base + it * (THREADS * 2);
        // two independent LDG.128 in flight (proven shape)
        float4 v0 = __ldcs(x + o);
        float4 v1 = __ldcs(x + o + THREADS);

        float xin0[4] = {v0.x, v0.y, v0.z, v0.w};
        float xin1[4] = {v1.x, v1.y, v1.z, v1.w};
        float r0[4], r1[4];
#pragma unroll
        for (int k = 0; k < 4; ++k) {
            float t  = xin0[k] * s25;                      // = xs / GRID
            float tc = fminf(fmaxf(t, TLO), THI);          // clamp in t-domain
            float fl = floorf(tc);                         // [-25, 24]
            float fr = t - fl;                             // frac from UNCLAMPED t
            int idx  = HALFI + (int)fl;                    // [0, 49]
            float2 p = tab[idx];                           // LDS.64 gather
            r0[k] = fmaf(fr, p.y, p.x) * inv_s;
        }
#pragma unroll
        for (int k = 0; k < 4; ++k) {
            float t  = xin1[k] * s25;
            float tc = fminf(fmaxf(t, TLO), THI);
            float fl = floorf(tc);
            float fr = t - fl;
            int idx  = HALFI + (int)fl;
            float2 p = tab[idx];
            r1[k] = fmaf(fr, p.y, p.x) * inv_s;
        }
        __stcs(out + o,           make_float4(r0[0], r0[1], r0[2], r0[3]));
        __stcs(out + o + THREADS, make_float4(r1[0], r1[1], r1[2], r1[3]));
    }
}

extern "C" void kernel_launch(void* const* d_in, const int* in_sizes, int n_in,
                              void* d_out, int out_size) {
    const float* x     = (const float*)d_in[0];
    const float* coeff = (const float*)d_in[1];
    const float* scl   = (const float*)d_in[2];
    float* out = (float*)d_out;

    int n  = out_size;                 // 33554432
    int blocks = n / (BLOCK_V4 * 4);   // 4096
    spline_fused_kernel<<<blocks, THREADS>>>((const float4*)x, coeff, scl,
                                             (float4*)out);
}

// round 10
// speedup vs baseline: 1.0520x; 1.0021x over previous
#include <cuda_runtime.h>

// LinearSpline: per-channel slope-clipped linear spline activation, fused.
// x: [32, 64, 128, 128] f32, coefficients_vect: [64*51] f32, scaling: [64] f32.
//
// Grid 8192 (4096 elems/block), 256 threads, 2 iterations x 2 front-batched
// float4/thread (proven body). Gather table stored as bank-strided 8-replica
// SoA (c0[], slope[]) so each 4-lane group gathers from its own 4-bank set:
// smem conflict degree ~2 instead of ~3.5, unpinning the LDS crossbar that
// capped DRAM at 69.8% across R6/R7/R9.

#define NCH   64
#define SZ    51
#define HALFI 25                               // SIZE // 2
#define GRID_D   (2.0 * 1.0 / (SZ - 1))        // 0.04 (double, matches python)
#define GRID_F   ((float)GRID_D)
#define TLO   (-25.0f)                         // clamp bounds in t = xs*25 domain
#define THI   ( 24.0f)

#define THREADS   256
#define BLOCK_V4  1024                         // 4096 elems / 4
#define ITERS     (BLOCK_V4 / (THREADS * 2))   // 2 iterations of 2 float4/thread

// Bank-strided replicated table: entry j, replica r at word (j>>2)*32 + 4r + (j&3).
// 50 entries -> 13 rows of 32 words = 416 words per array.
#define TAB_WORDS 416
__device__ __forceinline__ int woff(int j) { return j + 28 * (j >> 2); }

__global__ void __launch_bounds__(THREADS)
spline_fused_kernel(const float4* __restrict__ x,
                    const float*  __restrict__ coeff,
                    const float*  __restrict__ scale,
                    float4* __restrict__ out) {
    __shared__ float tabs[2 * TAB_WORDS];      // [0..415]=c0, [416..831]=slope
    __shared__ float sh_s[2];                  // {s*25, 1/s}

    // block covers 4096 elems; plane = 16384; c = (b>>2) & 63
    int c = (blockIdx.x >> 2) & (NCH - 1);

    // ---- table build: warp 0, shfl parallel scan + 8-replica scatter ------
    if (threadIdx.x < 32) {
        int lane = threadIdx.x;
        const float* cs = coeff + c * SZ;
        float a  = (2 * lane     <= 50) ? __ldg(cs + 2 * lane)     : 0.0f; // cs[2l]
        float bb = (2 * lane + 1 <= 50) ? __ldg(cs + 2 * lane + 1) : 0.0f; // cs[2l+1]
        float a_next = __shfl_down_sync(0xffffffff, a, 1);                 // cs[2l+2]
        float s_even = fminf(fmaxf(bb - a,      0.0f), GRID_F);  // slope[2l]
        float s_odd  = fminf(fmaxf(a_next - bb, 0.0f), GRID_F);  // slope[2l+1]
        float p = (lane <= 24) ? (s_even + s_odd) : 0.0f;
        float P = p;                                             // inclusive scan
#pragma unroll
        for (int off = 1; off < 32; off <<= 1) {
            float t = __shfl_up_sync(0xffffffff, P, off);
            if (lane >= off) P += t;
        }
        float v_even = P - p;                  // vals[2l]  (exclusive)
        float v_odd  = v_even + s_even;        // vals[2l+1]
        float mid = __shfl_sync(0xffffffff, v_odd, 12);   // vals[25]
        if (lane <= 24) {
            int w0 = woff(2 * lane);
            int w1 = woff(2 * lane + 1);
#pragma unroll
            for (int r = 0; r < 8; ++r) {
                int ro = r << 2;
                tabs[w0 + ro]             = v_even - mid;
                tabs[w1 + ro]             = v_odd  - mid;
                tabs[TAB_WORDS + w0 + ro] = s_even;
                tabs[TAB_WORDS + w1 + ro] = s_odd;
            }
        }
        if (lane == 0) {
            float s = __ldg(scale + c);
            sh_s[0] = s * 25.0f;               // fold 1/GRID into the scale
            sh_s[1] = __fdividef(1.0f, s);
        }
    }
    __syncthreads();

    float s25   = sh_s[0];
    float inv_s = sh_s[1];
    int lane4 = (threadIdx.x & 31) >> 2 << 2;  // replica word offset = 4*(lane/4)
    int base = blockIdx.x * BLOCK_V4 + threadIdx.x;

#pragma unroll
    for (int it = 0; it < ITERS; ++it) {
        int o = base + it * (THREADS * 2);
        // two independent LDG.128 in flight (proven shape)
        float4 v0 = __ldcs(x + o);
        float4 v1 = __ldcs(x + o + THREADS);

        float xin0[4] = {v0.x, v0.y, v0.z, v0.w};
        float xin1[4] = {v1.x, v1.y, v1.z, v1.w};
        float r0[4], r1[4];
#pragma unroll
        for (int k = 0; k < 4; ++k) {
            float t  = xin0[k] * s25;                      // = xs / GRID
            float tc = fminf(fmaxf(t, TLO), THI);          // clamp in t-domain
            float fl = floorf(tc);                         // [-25, 24]
            float fr = t - fl;                             // frac from UNCLAMPED t
            int idx  = HALFI + (int)fl;                    // [0, 49]
            int w    = woff(idx) + lane4;                  // bank-strided, replica-local
            r0[k] = fmaf(fr, tabs[TAB_WORDS + w], tabs[w]) * inv_s;
        }
#pragma unroll
        for (int k = 0; k < 4; ++k) {
            float t  = xin1[k] * s25;
            float tc = fminf(fmaxf(t, TLO), THI);
            float fl = floorf(tc);
            float fr = t - fl;
            int idx  = HALFI + (int)fl;
            int w    = woff(idx) + lane4;
            r1[k] = fmaf(fr, tabs[TAB_WORDS + w], tabs[w]) * inv_s;
        }
        __stcs(out + o,           make_float4(r0[0], r0[1], r0[2], r0[3]));
        __stcs(out + o + THREADS, make_float4(r1[0], r1[1], r1[2], r1[3]));
    }
}

extern "C" void kernel_launch(void* const* d_in, const int* in_sizes, int n_in,
                              void* d_out, int out_size) {
    const float* x     = (const float*)d_in[0];
    const float* coeff = (const float*)d_in[1];
    const float* scl   = (const float*)d_in[2];
    float* out = (float*)d_out;

    int n  = out_size;                 // 33554432
    int blocks = n / (BLOCK_V4 * 4);   // 8192
    spline_fused_kernel<<<blocks, THREADS>>>((const float4*)x, coeff, scl,
                                             (float4*)out);
}

// round 11
// speedup vs baseline: 1.0602x; 1.0078x over previous
#include <cuda_runtime.h>

// LinearSpline: per-channel slope-clipped linear spline activation, fused.
// x: [32, 64, 128, 128] f32, coefficients_vect: [64*51] f32, scaling: [64] f32.
//
// Combination of the two measured optima:
//  - inner body from R9: single float2 LDS.64 gather, t-domain math,
//    2 front-batched LDG.128 per iteration, regs 32, occ ~83%
//  - granularity from R10: grid 8192 (4096 elems/block), where the
//    wall-vs-kernel replay gap is minimal (~3.1us vs 6.7us at grid 4096)

#define NCH   64
#define SZ    51
#define HALFI 25                               // SIZE // 2
#define GRID_D   (2.0 * 1.0 / (SZ - 1))        // 0.04 (double, matches python)
#define GRID_F   ((float)GRID_D)
#define TLO   (-25.0f)                         // clamp bounds in t = xs*25 domain
#define THI   ( 24.0f)

#define THREADS   256
#define BLOCK_V4  1024                         // 4096 elems / 4
#define ITERS     (BLOCK_V4 / (THREADS * 2))   // 2 iterations of 2 float4/thread

__global__ void __launch_bounds__(THREADS)
spline_fused_kernel(const float4* __restrict__ x,
                    const float*  __restrict__ coeff,
                    const float*  __restrict__ scale,
                    float4* __restrict__ out) {
    __shared__ float2 tab[SZ - 1];             // {c0, slope} per interval
    __shared__ float  sh_s[2];                 // {s*25, 1/s}

    // block covers 4096 elems; plane = 16384; c = (b>>2) & 63
    int c = (blockIdx.x >> 2) & (NCH - 1);

    // ---- table build, once per block: warp 0, shfl parallel scan ----------
    if (threadIdx.x < 32) {
        int lane = threadIdx.x;
        const float* cs = coeff + c * SZ;
        float a  = (2 * lane     <= 50) ? __ldg(cs + 2 * lane)     : 0.0f; // cs[2l]
        float bb = (2 * lane + 1 <= 50) ? __ldg(cs + 2 * lane + 1) : 0.0f; // cs[2l+1]
        float a_next = __shfl_down_sync(0xffffffff, a, 1);                 // cs[2l+2]
        float s_even = fminf(fmaxf(bb - a,      0.0f), GRID_F);  // slope[2l]
        float s_odd  = fminf(fmaxf(a_next - bb, 0.0f), GRID_F);  // slope[2l+1]
        float p = (lane <= 24) ? (s_even + s_odd) : 0.0f;
        float P = p;                                             // inclusive scan
#pragma unroll
        for (int off = 1; off < 32; off <<= 1) {
            float t = __shfl_up_sync(0xffffffff, P, off);
            if (lane >= off) P += t;
        }
        float v_even = P - p;                  // vals[2l]  (exclusive)
        float v_odd  = v_even + s_even;        // vals[2l+1]
        float mid = __shfl_sync(0xffffffff, v_odd, 12);   // vals[25]
        if (lane <= 24) {
            tab[2 * lane]     = make_float2(v_even - mid, s_even);
            tab[2 * lane + 1] = make_float2(v_odd  - mid, s_odd);
        }
        if (lane == 0) {
            float s = __ldg(scale + c);
            sh_s[0] = s * 25.0f;               // fold 1/GRID into the scale
            sh_s[1] = __fdividef(1.0f, s);
        }
    }
    __syncthreads();

    float s25   = sh_s[0];
    float inv_s = sh_s[1];
    int base = blockIdx.x * BLOCK_V4 + threadIdx.x;

#pragma unroll
    for (int it = 0; it < ITERS; ++it) {
        int o = base + it * (THREADS * 2);
        // two independent LDG.128 in flight (proven shape)
        float4 v0 = __ldcs(x + o);
        float4 v1 = __ldcs(x + o + THREADS);

        float xin0[4] = {v0.x, v0.y, v0.z, v0.w};
        float xin1[4] = {v1.x, v1.y, v1.z, v1.w};
        float r0[4], r1[4];
#pragma unroll
        for (int k = 0; k < 4; ++k) {
            float t  = xin0[k] * s25;                      // = xs / GRID
            float tc = fminf(fmaxf(t, TLO), THI);          // clamp in t-domain
            float fl = floorf(tc);                         // [-25, 24]
            float fr = t - fl;                             // frac from UNCLAMPED t
            int idx  = HALFI + (int)fl;                    // [0, 49]
            float2 p = tab[idx];                           // LDS.64 gather
            r0[k] = fmaf(fr, p.y, p.x) * inv_s;
        }
#pragma unroll
        for (int k = 0; k < 4; ++k) {
            float t  = xin1[k] * s25;
            float tc = fminf(fmaxf(t, TLO), THI);
            float fl = floorf(tc);
            float fr = t - fl;
            int idx  = HALFI + (int)fl;
            float2 p = tab[idx];
            r1[k] = fmaf(fr, p.y, p.x) * inv_s;
        }
        __stcs(out + o,           make_float4(r0[0], r0[1], r0[2], r0[3]));
        __stcs(out + o + THREADS, make_float4(r1[0], r1[1], r1[2], r1[3]));
    }
}

extern "C" void kernel_launch(void* const* d_in, const int* in_sizes, int n_in,
                              void* d_out, int out_size) {
    const float* x     = (const float*)d_in[0];
    const float* coeff = (const float*)d_in[1];
    const float* scl   = (const float*)d_in[2];
    float* out = (float*)d_out;

    int n  = out_size;                 // 33554432
    int blocks = n / (BLOCK_V4 * 4);   // 8192
    spline_fused_kernel<<<blocks, THREADS>>>((const float4*)x, coeff, scl,
                                             (float4*)out);
}

// round 12
// speedup vs baseline: 1.0610x; 1.0007x over previous
#include <cuda_runtime.h>

// LinearSpline: per-channel slope-clipped linear spline activation, fused.
// x: [32, 64, 128, 128] f32, coefficients_vect: [64*51] f32, scaling: [64] f32.
//
// Grid 8192, 256 threads, 2 iters x 2 front-batched float4/thread (proven).
// NEW: no __syncthreads at all. Every warp builds its OWN 50-entry
// {value, slope} table via shfl scan into a private smem region (only a
// __syncwarp orders it), and iteration-0 global loads are issued BEFORE the
// build so DRAM latency overlaps the scan. Block prologue serialization gone.

#define NCH   64
#define SZ    51
#define HALFI 25                               // SIZE // 2
#define GRID_D   (2.0 * 1.0 / (SZ - 1))        // 0.04 (double, matches python)
#define GRID_F   ((float)GRID_D)
#define TLO   (-25.0f)                         // clamp bounds in t = xs*25 domain
#define THI   ( 24.0f)

#define THREADS   256
#define NWARPS    (THREADS / 32)
#define BLOCK_V4  1024                         // 4096 elems / 4

__global__ void __launch_bounds__(THREADS)
spline_fused_kernel(const float4* __restrict__ x,
                    const float*  __restrict__ coeff,
                    const float*  __restrict__ scale,
                    float4* __restrict__ out) {
    __shared__ float2 tabs[NWARPS][SZ - 1];    // per-warp private {c0, slope}

    int lane = threadIdx.x & 31;
    int wid  = threadIdx.x >> 5;
    float2* __restrict__ mytab = tabs[wid];

    // block covers 4096 elems; plane = 16384; c = (b>>2) & 63
    int c = (blockIdx.x >> 2) & (NCH - 1);

    int base = blockIdx.x * BLOCK_V4 + threadIdx.x;

    // ---- iteration-0 loads FIRST: overlap DRAM latency with table build ----
    float4 v0 = __ldcs(x + base);
    float4 v1 = __ldcs(x + base + THREADS);

    // ---- per-warp table build: shfl parallel scan (no block barrier) -------
    {
        const float* cs = coeff + c * SZ;
        float a  = (2 * lane     <= 50) ? __ldg(cs + 2 * lane)     : 0.0f; // cs[2l]
        float bb = (2 * lane + 1 <= 50) ? __ldg(cs + 2 * lane + 1) : 0.0f; // cs[2l+1]
        float a_next = __shfl_down_sync(0xffffffff, a, 1);                 // cs[2l+2]
        float s_even = fminf(fmaxf(bb - a,      0.0f), GRID_F);  // slope[2l]
        float s_odd  = fminf(fmaxf(a_next - bb, 0.0f), GRID_F);  // slope[2l+1]
        float p = (lane <= 24) ? (s_even + s_odd) : 0.0f;
        float P = p;                                             // inclusive scan
#pragma unroll
        for (int off = 1; off < 32; off <<= 1) {
            float t = __shfl_up_sync(0xffffffff, P, off);
            if (lane >= off) P += t;
        }
        float v_even = P - p;                  // vals[2l]  (exclusive)
        float v_odd  = v_even + s_even;        // vals[2l+1]
        float mid = __shfl_sync(0xffffffff, v_odd, 12);   // vals[25]
        if (lane <= 24) {
            mytab[2 * lane]     = make_float2(v_even - mid, s_even);
            mytab[2 * lane + 1] = make_float2(v_odd  - mid, s_odd);
        }
    }
    // scale broadcast in registers (no smem, no block sync)
    float s = __shfl_sync(0xffffffff,
                          (lane == 0) ? __ldg(scale + c) : 0.0f, 0);
    float s25   = s * 25.0f;                   // fold 1/GRID into the scale
    float inv_s = __fdividef(1.0f, s);
    __syncwarp();                              // order STS -> LDS within warp

    // ---- iteration 0 ---------------------------------------------------------
    {
        float xin0[4] = {v0.x, v0.y, v0.z, v0.w};
        float xin1[4] = {v1.x, v1.y, v1.z, v1.w};
        float r0[4], r1[4];
#pragma unroll
        for (int k = 0; k < 4; ++k) {
            float t  = xin0[k] * s25;                      // = xs / GRID
            float tc = fminf(fmaxf(t, TLO), THI);          // clamp in t-domain
            float fl = floorf(tc);                         // [-25, 24]
            float fr = t - fl;                             // frac from UNCLAMPED t
            int idx  = HALFI + (int)fl;                    // [0, 49]
            float2 p = mytab[idx];                         // LDS.64 gather
            r0[k] = fmaf(fr, p.y, p.x) * inv_s;
        }
#pragma unroll
        for (int k = 0; k < 4; ++k) {
            float t  = xin1[k] * s25;
            float tc = fminf(fmaxf(t, TLO), THI);
            float fl = floorf(tc);
            float fr = t - fl;
            int idx  = HALFI + (int)fl;
            float2 p = mytab[idx];
            r1[k] = fmaf(fr, p.y, p.x) * inv_s;
        }
        __stcs(out + base,           make_float4(r0[0], r0[1], r0[2], r0[3]));
        __stcs(out + base + THREADS, make_float4(r1[0], r1[1], r1[2], r1[3]));
    }

    // ---- iteration 1 ---------------------------------------------------------
    {
        int o = base + THREADS * 2;
        float4 w0 = __ldcs(x + o);
        float4 w1 = __ldcs(x + o + THREADS);

        float xin0[4] = {w0.x, w0.y, w0.z, w0.w};
        float xin1[4] = {w1.x, w1.y, w1.z, w1.w};
        float r0[4], r1[4];
#pragma unroll
        for (int k = 0; k < 4; ++k) {
            float t  = xin0[k] * s25;
            float tc = fminf(fmaxf(t, TLO), THI);
            float fl = floorf(tc);
            float fr = t - fl;
            int idx  = HALFI + (int)fl;
            float2 p = mytab[idx];
            r0[k] = fmaf(fr, p.y, p.x) * inv_s;
        }
#pragma unroll
        for (int k = 0; k < 4; ++k) {
            float t  = xin1[k] * s25;
            float tc = fminf(fmaxf(t, TLO), THI);
            float fl = floorf(tc);
            float fr = t - fl;
            int idx  = HALFI + (int)fl;
            float2 p = mytab[idx];
            r1[k] = fmaf(fr, p.y, p.x) * inv_s;
        }
        __stcs(out + o,           make_float4(r0[0], r0[1], r0[2], r0[3]));
        __stcs(out + o + THREADS, make_float4(r1[0], r1[1], r1[2], r1[3]));
    }
}

extern "C" void kernel_launch(void* const* d_in, const int* in_sizes, int n_in,
                              void* d_out, int out_size) {
    const float* x     = (const float*)d_in[0];
    const float* coeff = (const float*)d_in[1];
    const float* scl   = (const float*)d_in[2];
    float* out = (float*)d_out;

    int n  = out_size;                 // 33554432
    int blocks = n / (BLOCK_V4 * 4);   // 8192
    spline_fused_kernel<<<blocks, THREADS>>>((const float4*)x, coeff, scl,
                                             (float4*)out);
}

// round 13
// speedup vs baseline: 1.0617x; 1.0007x over previous
#include <cuda_runtime.h>

// LinearSpline: per-channel slope-clipped linear spline activation, fused.
// x: [32, 64, 128, 128] f32, coefficients_vect: [64*51] f32, scaling: [64] f32.
//
// Final composition of measured optima:
//  - grid 8192 (4096 elems/block), 256 threads, 2 iters x 2 float4/thread
//  - single shared {c0, slope} table built by warp 0 shfl scan (R11: lowest
//    L1 traffic) -- NOT per-warp (R12 regressed L1 to 72%)
//  - iteration-0 LDG.128s hoisted ABOVE the build + barrier (R12-validated):
//    DRAM latency overlaps the table build, warps consume hot data after sync
//  - t-domain math: t = x*(s*25); clamp [-25,24]; frac from unclamped t

#define NCH   64
#define SZ    51
#define HALFI 25                               // SIZE // 2
#define GRID_D   (2.0 * 1.0 / (SZ - 1))        // 0.04 (double, matches python)
#define GRID_F   ((float)GRID_D)
#define TLO   (-25.0f)                         // clamp bounds in t = xs*25 domain
#define THI   ( 24.0f)

#define THREADS   256
#define BLOCK_V4  1024                         // 4096 elems / 4

__global__ void __launch_bounds__(THREADS)
spline_fused_kernel(const float4* __restrict__ x,
                    const float*  __restrict__ coeff,
                    const float*  __restrict__ scale,
                    float4* __restrict__ out) {
    __shared__ float2 tab[SZ - 1];             // {c0, slope} per interval
    __shared__ float  sh_s[2];                 // {s*25, 1/s}

    // block covers 4096 elems; plane = 16384; c = (b>>2) & 63
    int c = (blockIdx.x >> 2) & (NCH - 1);
    int base = blockIdx.x * BLOCK_V4 + threadIdx.x;

    // ---- iteration-0 loads FIRST: DRAM latency overlaps the table build ----
    float4 v0 = __ldcs(x + base);
    float4 v1 = __ldcs(x + base + THREADS);

    // ---- table build: warp 0 only, shfl parallel scan ----------------------
    if (threadIdx.x < 32) {
        int lane = threadIdx.x;
        const float* cs = coeff + c * SZ;
        float a  = (2 * lane     <= 50) ? __ldg(cs + 2 * lane)     : 0.0f; // cs[2l]
        float bb = (2 * lane + 1 <= 50) ? __ldg(cs + 2 * lane + 1) : 0.0f; // cs[2l+1]
        float a_next = __shfl_down_sync(0xffffffff, a, 1);                 // cs[2l+2]
        float s_even = fminf(fmaxf(bb - a,      0.0f), GRID_F);  // slope[2l]
        float s_odd  = fminf(fmaxf(a_next - bb, 0.0f), GRID_F);  // slope[2l+1]
        float p = (lane <= 24) ? (s_even + s_odd) : 0.0f;
        float P = p;                                             // inclusive scan
#pragma unroll
        for (int off = 1; off < 32; off <<= 1) {
            float t = __shfl_up_sync(0xffffffff, P, off);
            if (lane >= off) P += t;
        }
        float v_even = P - p;                  // vals[2l]  (exclusive)
        float v_odd  = v_even + s_even;        // vals[2l+1]
        float mid = __shfl_sync(0xffffffff, v_odd, 12);   // vals[25]
        if (lane <= 24) {
            tab[2 * lane]     = make_float2(v_even - mid, s_even);
            tab[2 * lane + 1] = make_float2(v_odd  - mid, s_odd);
        }
        if (lane == 0) {
            float s = __ldg(scale + c);
            sh_s[0] = s * 25.0f;               // fold 1/GRID into the scale
            sh_s[1] = __fdividef(1.0f, s);
        }
    }
    __syncthreads();

    float s25   = sh_s[0];
    float inv_s = sh_s[1];

    // ---- iteration 0 (data already in flight / arrived) --------------------
    {
        float xin0[4] = {v0.x, v0.y, v0.z, v0.w};
        float xin1[4] = {v1.x, v1.y, v1.z, v1.w};
        float r0[4], r1[4];
#pragma unroll
        for (int k = 0; k < 4; ++k) {
            float t  = xin0[k] * s25;                      // = xs / GRID
            float tc = fminf(fmaxf(t, TLO), THI);          // clamp in t-domain
            float fl = floorf(tc);                         // [-25, 24]
            float fr = t - fl;                             // frac from UNCLAMPED t
            int idx  = HALFI + (int)fl;                    // [0, 49]
            float2 p = tab[idx];                           // LDS.64 gather
            r0[k] = fmaf(fr, p.y, p.x) * inv_s;
        }
#pragma unroll
        for (int k = 0; k < 4; ++k) {
            float t  = xin1[k] * s25;
            float tc = fminf(fmaxf(t, TLO), THI);
            float fl = floorf(tc);
            float fr = t - fl;
            int idx  = HALFI + (int)fl;
            float2 p = tab[idx];
            r1[k] = fmaf(fr, p.y, p.x) * inv_s;
        }
        __stcs(out + base,           make_float4(r0[0], r0[1], r0[2], r0[3]));
        __stcs(out + base + THREADS, make_float4(r1[0], r1[1], r1[2], r1[3]));
    }

    // ---- iteration 1 --------------------------------------------------------
    {
        int o = base + THREADS * 2;
        float4 w0 = __ldcs(x + o);
        float4 w1 = __ldcs(x + o + THREADS);

        float xin0[4] = {w0.x, w0.y, w0.z, w0.w};
        float xin1[4] = {w1.x, w1.y, w1.z, w1.w};
        float r0[4], r1[4];
#pragma unroll
        for (int k = 0; k < 4; ++k) {
            float t  = xin0[k] * s25;
            float tc = fminf(fmaxf(t, TLO), THI);
            float fl = floorf(tc);
            float fr = t - fl;
            int idx  = HALFI + (int)fl;
            float2 p = tab[idx];
            r0[k] = fmaf(fr, p.y, p.x) * inv_s;
        }
#pragma unroll
        for (int k = 0; k < 4; ++k) {
            float t  = xin1[k] * s25;
            float tc = fminf(fmaxf(t, TLO), THI);
            float fl = floorf(tc);
            float fr = t - fl;
            int idx  = HALFI + (int)fl;
            float2 p = tab[idx];
            r1[k] = fmaf(fr, p.y, p.x) * inv_s;
        }
        __stcs(out + o,           make_float4(r0[0], r0[1], r0[2], r0[3]));
        __stcs(out + o + THREADS, make_float4(r1[0], r1[1], r1[2], r1[3]));
    }
}

extern "C" void kernel_launch(void* const* d_in, const int* in_sizes, int n_in,
                              void* d_out, int out_size) {
    const float* x     = (const float*)d_in[0];
    const float* coeff = (const float*)d_in[1];
    const float* scl   = (const float*)d_in[2];
    float* out = (float*)d_out;

    int n  = out_size;                 // 33554432
    int blocks = n / (BLOCK_V4 * 4);   // 8192
    spline_fused_kernel<<<blocks, THREADS>>>((const float4*)x, coeff, scl,
                                             (float4*)out);
}

// round 14
// speedup vs baseline: 1.0716x; 1.0093x over previous
#include <cuda_runtime.h>

// LinearSpline: per-channel slope-clipped linear spline activation, fused.
// x: [32, 64, 128, 128] f32, coefficients_vect: [64*51] f32, scaling: [64] f32.
//
// R13 + full load front-batch: ALL FOUR LDG.128s issue before the table-build
// barrier (launch_bounds(256,6) caps regs at 42 so the 16 data regs stay live
// without the R8-style 63-reg occupancy cliff). The block's entire read
// traffic overlaps the warp-0 shfl-scan table build; post-barrier both
// iterations consume arrived data back-to-back.

#define NCH   64
#define SZ    51
#define HALFI 25                               // SIZE // 2
#define GRID_D   (2.0 * 1.0 / (SZ - 1))        // 0.04 (double, matches python)
#define GRID_F   ((float)GRID_D)
#define TLO   (-25.0f)                         // clamp bounds in t = xs*25 domain
#define THI   ( 24.0f)

#define THREADS   256
#define BLOCK_V4  1024                         // 4096 elems / 4

__global__ void __launch_bounds__(THREADS, 6)   // reg cap 42: room for 4 live float4
spline_fused_kernel(const float4* __restrict__ x,
                    const float*  __restrict__ coeff,
                    const float*  __restrict__ scale,
                    float4* __restrict__ out) {
    __shared__ float2 tab[SZ - 1];             // {c0, slope} per interval
    __shared__ float  sh_s[2];                 // {s*25, 1/s}

    // block covers 4096 elems; plane = 16384; c = (b>>2) & 63
    int c = (blockIdx.x >> 2) & (NCH - 1);
    int base = blockIdx.x * BLOCK_V4 + threadIdx.x;

    // ---- ALL loads first: whole block's read traffic in flight -------------
    float4 v0 = __ldcs(x + base);
    float4 v1 = __ldcs(x + base + THREADS);
    float4 v2 = __ldcs(x + base + THREADS * 2);
    float4 v3 = __ldcs(x + base + THREADS * 3);

    // ---- table build: warp 0 only, shfl parallel scan ----------------------
    if (threadIdx.x < 32) {
        int lane = threadIdx.x;
        const float* cs = coeff + c * SZ;
        float a  = (2 * lane     <= 50) ? __ldg(cs + 2 * lane)     : 0.0f; // cs[2l]
        float bb = (2 * lane + 1 <= 50) ? __ldg(cs + 2 * lane + 1) : 0.0f; // cs[2l+1]
        float a_next = __shfl_down_sync(0xffffffff, a, 1);                 // cs[2l+2]
        float s_even = fminf(fmaxf(bb - a,      0.0f), GRID_F);  // slope[2l]
        float s_odd  = fminf(fmaxf(a_next - bb, 0.0f), GRID_F);  // slope[2l+1]
        float p = (lane <= 24) ? (s_even + s_odd) : 0.0f;
        float P = p;                                             // inclusive scan
#pragma unroll
        for (int off = 1; off < 32; off <<= 1) {
            float t = __shfl_up_sync(0xffffffff, P, off);
            if (lane >= off) P += t;
        }
        float v_even = P - p;                  // vals[2l]  (exclusive)
        float v_odd  = v_even + s_even;        // vals[2l+1]
        float mid = __shfl_sync(0xffffffff, v_odd, 12);   // vals[25]
        if (lane <= 24) {
            tab[2 * lane]     = make_float2(v_even - mid, s_even);
            tab[2 * lane + 1] = make_float2(v_odd  - mid, s_odd);
        }
        if (lane == 0) {
            float s = __ldg(scale + c);
            sh_s[0] = s * 25.0f;               // fold 1/GRID into the scale
            sh_s[1] = __fdividef(1.0f, s);
        }
    }
    __syncthreads();

    float s25   = sh_s[0];
    float inv_s = sh_s[1];

    // ---- evaluate + store, pairwise (frees v-regs as we go) ----------------
    {
        float xin0[4] = {v0.x, v0.y, v0.z, v0.w};
        float xin1[4] = {v1.x, v1.y, v1.z, v1.w};
        float r0[4], r1[4];
#pragma unroll
        for (int k = 0; k < 4; ++k) {
            float t  = xin0[k] * s25;                      // = xs / GRID
            float tc = fminf(fmaxf(t, TLO), THI);          // clamp in t-domain
            float fl = floorf(tc);                         // [-25, 24]
            float fr = t - fl;                             // frac from UNCLAMPED t
            int idx  = HALFI + (int)fl;                    // [0, 49]
            float2 p = tab[idx];                           // LDS.64 gather
            r0[k] = fmaf(fr, p.y, p.x) * inv_s;
        }
#pragma unroll
        for (int k = 0; k < 4; ++k) {
            float t  = xin1[k] * s25;
            float tc = fminf(fmaxf(t, TLO), THI);
            float fl = floorf(tc);
            float fr = t - fl;
            int idx  = HALFI + (int)fl;
            float2 p = tab[idx];
            r1[k] = fmaf(fr, p.y, p.x) * inv_s;
        }
        __stcs(out + base,           make_float4(r0[0], r0[1], r0[2], r0[3]));
        __stcs(out + base + THREADS, make_float4(r1[0], r1[1], r1[2], r1[3]));
    }
    {
        float xin0[4] = {v2.x, v2.y, v2.z, v2.w};
        float xin1[4] = {v3.x, v3.y, v3.z, v3.w};
        float r0[4], r1[4];
#pragma unroll
        for (int k = 0; k < 4; ++k) {
            float t  = xin0[k] * s25;
            float tc = fminf(fmaxf(t, TLO), THI);
            float fl = floorf(tc);
            float fr = t - fl;
            int idx  = HALFI + (int)fl;
            float2 p = tab[idx];
            r0[k] = fmaf(fr, p.y, p.x) * inv_s;
        }
#pragma unroll
        for (int k = 0; k < 4; ++k) {
            float t  = xin1[k] * s25;
            float tc = fminf(fmaxf(t, TLO), THI);
            float fl = floorf(tc);
            float fr = t - fl;
            int idx  = HALFI + (int)fl;
            float2 p = tab[idx];
            r1[k] = fmaf(fr, p.y, p.x) * inv_s;
        }
        __stcs(out + base + THREADS * 2, make_float4(r0[0], r0[1], r0[2], r0[3]));
        __stcs(out + base + THREADS * 3, make_float4(r1[0], r1[1], r1[2], r1[3]));
    }
}

extern "C" void kernel_launch(void* const* d_in, const int* in_sizes, int n_in,
                              void* d_out, int out_size) {
    const float* x     = (const float*)d_in[0];
    const float* coeff = (const float*)d_in[1];
    const float* scl   = (const float*)d_in[2];
    float* out = (float*)d_out;

    int n  = out_size;                 // 33554432
    int blocks = n / (BLOCK_V4 * 4);   // 8192
    spline_fused_kernel<<<blocks, THREADS>>>((const float4*)x, coeff, scl,
                                             (float4*)out);
}

// round 15
// speedup vs baseline: 1.0833x; 1.0109x over previous
#include <cuda_runtime.h>

// LinearSpline: per-channel slope-clipped linear spline activation, fused.
// x: [32, 64, 128, 128] f32, coefficients_vect: [64*51] f32, scaling: [64] f32.
//
// R14 structure (4 front-batched LDG.128 before the table-build barrier,
// reg cap 42) at 128-thread blocks: barrier scope 4 warps instead of 8,
// 12 blocks/SM, grid 16384 for finer wave quantization. Block = 2048 elems
// (one 16384-elem plane = 8 blocks): channel = (b>>3) & 63.

#define NCH   64
#define SZ    51
#define HALFI 25                               // SIZE // 2
#define GRID_D   (2.0 * 1.0 / (SZ - 1))        // 0.04 (double, matches python)
#define GRID_F   ((float)GRID_D)
#define TLO   (-25.0f)                         // clamp bounds in t = xs*25 domain
#define THI   ( 24.0f)

#define THREADS   128
#define BLOCK_V4  512                          // 2048 elems / 4

__global__ void __launch_bounds__(THREADS, 12)  // reg cap 42 (matches R14's 40)
spline_fused_kernel(const float4* __restrict__ x,
                    const float*  __restrict__ coeff,
                    const float*  __restrict__ scale,
                    float4* __restrict__ out) {
    __shared__ float2 tab[SZ - 1];             // {c0, slope} per interval
    __shared__ float  sh_s[2];                 // {s*25, 1/s}

    // block covers 2048 elems; plane = 16384; c = (b>>3) & 63
    int c = (blockIdx.x >> 3) & (NCH - 1);
    int base = blockIdx.x * BLOCK_V4 + threadIdx.x;

    // ---- ALL loads first: whole block's read traffic in flight -------------
    float4 v0 = __ldcs(x + base);
    float4 v1 = __ldcs(x + base + THREADS);
    float4 v2 = __ldcs(x + base + THREADS * 2);
    float4 v3 = __ldcs(x + base + THREADS * 3);

    // ---- table build: warp 0 only, shfl parallel scan ----------------------
    if (threadIdx.x < 32) {
        int lane = threadIdx.x;
        const float* cs = coeff + c * SZ;
        float a  = (2 * lane     <= 50) ? __ldg(cs + 2 * lane)     : 0.0f; // cs[2l]
        float bb = (2 * lane + 1 <= 50) ? __ldg(cs + 2 * lane + 1) : 0.0f; // cs[2l+1]
        float a_next = __shfl_down_sync(0xffffffff, a, 1);                 // cs[2l+2]
        float s_even = fminf(fmaxf(bb - a,      0.0f), GRID_F);  // slope[2l]
        float s_odd  = fminf(fmaxf(a_next - bb, 0.0f), GRID_F);  // slope[2l+1]
        float p = (lane <= 24) ? (s_even + s_odd) : 0.0f;
        float P = p;                                             // inclusive scan
#pragma unroll
        for (int off = 1; off < 32; off <<= 1) {
            float t = __shfl_up_sync(0xffffffff, P, off);
            if (lane >= off) P += t;
        }
        float v_even = P - p;                  // vals[2l]  (exclusive)
        float v_odd  = v_even + s_even;        // vals[2l+1]
        float mid = __shfl_sync(0xffffffff, v_odd, 12);   // vals[25]
        if (lane <= 24) {
            tab[2 * lane]     = make_float2(v_even - mid, s_even);
            tab[2 * lane + 1] = make_float2(v_odd  - mid, s_odd);
        }
        if (lane == 0) {
            float s = __ldg(scale + c);
            sh_s[0] = s * 25.0f;               // fold 1/GRID into the scale
            sh_s[1] = __fdividef(1.0f, s);
        }
    }
    __syncthreads();

    float s25   = sh_s[0];
    float inv_s = sh_s[1];

    // ---- evaluate + store, pairwise (frees v-regs as we go) ----------------
    {
        float xin0[4] = {v0.x, v0.y, v0.z, v0.w};
        float xin1[4] = {v1.x, v1.y, v1.z, v1.w};
        float r0[4], r1[4];
#pragma unroll
        for (int k = 0; k < 4; ++k) {
            float t  = xin0[k] * s25;                      // = xs / GRID
            float tc = fminf(fmaxf(t, TLO), THI);          // clamp in t-domain
            float fl = floorf(tc);                         // [-25, 24]
            float fr = t - fl;                             // frac from UNCLAMPED t
            int idx  = HALFI + (int)fl;                    // [0, 49]
            float2 p = tab[idx];                           // LDS.64 gather
            r0[k] = fmaf(fr, p.y, p.x) * inv_s;
        }
#pragma unroll
        for (int k = 0; k < 4; ++k) {
            float t  = xin1[k] * s25;
            float tc = fminf(fmaxf(t, TLO), THI);
            float fl = floorf(tc);
            float fr = t - fl;
            int idx  = HALFI + (int)fl;
            float2 p = tab[idx];
            r1[k] = fmaf(fr, p.y, p.x) * inv_s;
        }
        __stcs(out + base,           make_float4(r0[0], r0[1], r0[2], r0[3]));
        __stcs(out + base + THREADS, make_float4(r1[0], r1[1], r1[2], r1[3]));
    }
    {
        float xin0[4] = {v2.x, v2.y, v2.z, v2.w};
        float xin1[4] = {v3.x, v3.y, v3.z, v3.w};
        float r0[4], r1[4];
#pragma unroll
        for (int k = 0; k < 4; ++k) {
            float t  = xin0[k] * s25;
            float tc = fminf(fmaxf(t, TLO), THI);
            float fl = floorf(tc);
            float fr = t - fl;
            int idx  = HALFI + (int)fl;
            float2 p = tab[idx];
            r0[k] = fmaf(fr, p.y, p.x) * inv_s;
        }
#pragma unroll
        for (int k = 0; k < 4; ++k) {
            float t  = xin1[k] * s25;
            float tc = fminf(fmaxf(t, TLO), THI);
            float fl = floorf(tc);
            float fr = t - fl;
            int idx  = HALFI + (int)fl;
            float2 p = tab[idx];
            r1[k] = fmaf(fr, p.y, p.x) * inv_s;
        }
        __stcs(out + base + THREADS * 2, make_float4(r0[0], r0[1], r0[2], r0[3]));
        __stcs(out + base + THREADS * 3, make_float4(r1[0], r1[1], r1[2], r1[3]));
    }
}

extern "C" void kernel_launch(void* const* d_in, const int* in_sizes, int n_in,
                              void* d_out, int out_size) {
    const float* x     = (const float*)d_in[0];
    const float* coeff = (const float*)d_in[1];
    const float* scl   = (const float*)d_in[2];
    float* out = (float*)d_out;

    int n  = out_size;                 // 33554432
    int blocks = n / (BLOCK_V4 * 4);   // 16384
    spline_fused_kernel<<<blocks, THREADS>>>((const float4*)x, coeff, scl,
                                             (float4*)out);
}

// round 16
// speedup vs baseline: 1.1000x; 1.0154x over previous
#include <cuda_runtime.h>

// LinearSpline: per-channel slope-clipped linear spline activation, fused.
// x: [32, 64, 128, 128] f32, coefficients_vect: [64*51] f32, scaling: [64] f32.
//
// R15 structure (4 front-batched LDG.128 before the table-build barrier,
// reg cap ~42) at 64-thread blocks: barrier scope is now a single sibling
// warp, grid 32768 for the finest wave quantization. Block = 1024 elems
// (one 16384-elem plane = 16 blocks): channel = (b>>4) & 63.

#define NCH   64
#define SZ    51
#define HALFI 25                               // SIZE // 2
#define GRID_D   (2.0 * 1.0 / (SZ - 1))        // 0.04 (double, matches python)
#define GRID_F   ((float)GRID_D)
#define TLO   (-25.0f)                         // clamp bounds in t = xs*25 domain
#define THI   ( 24.0f)

#define THREADS   64
#define BLOCK_V4  256                          // 1024 elems / 4

__global__ void __launch_bounds__(THREADS, 24)  // reg cap 42 (R14/R15 compile at 40)
spline_fused_kernel(const float4* __restrict__ x,
                    const float*  __restrict__ coeff,
                    const float*  __restrict__ scale,
                    float4* __restrict__ out) {
    __shared__ float2 tab[SZ - 1];             // {c0, slope} per interval
    __shared__ float  sh_s[2];                 // {s*25, 1/s}

    // block covers 1024 elems; plane = 16384; c = (b>>4) & 63
    int c = (blockIdx.x >> 4) & (NCH - 1);
    int base = blockIdx.x * BLOCK_V4 + threadIdx.x;

    // ---- ALL loads first: whole block's read traffic in flight -------------
    float4 v0 = __ldcs(x + base);
    float4 v1 = __ldcs(x + base + THREADS);
    float4 v2 = __ldcs(x + base + THREADS * 2);
    float4 v3 = __ldcs(x + base + THREADS * 3);

    // ---- table build: warp 0 only, shfl parallel scan ----------------------
    if (threadIdx.x < 32) {
        int lane = threadIdx.x;
        const float* cs = coeff + c * SZ;
        float a  = (2 * lane     <= 50) ? __ldg(cs + 2 * lane)     : 0.0f; // cs[2l]
        float bb = (2 * lane + 1 <= 50) ? __ldg(cs + 2 * lane + 1) : 0.0f; // cs[2l+1]
        float a_next = __shfl_down_sync(0xffffffff, a, 1);                 // cs[2l+2]
        float s_even = fminf(fmaxf(bb - a,      0.0f), GRID_F);  // slope[2l]
        float s_odd  = fminf(fmaxf(a_next - bb, 0.0f), GRID_F);  // slope[2l+1]
        float p = (lane <= 24) ? (s_even + s_odd) : 0.0f;
        float P = p;                                             // inclusive scan
#pragma unroll
        for (int off = 1; off < 32; off <<= 1) {
            float t = __shfl_up_sync(0xffffffff, P, off);
            if (lane >= off) P += t;
        }
        float v_even = P - p;                  // vals[2l]  (exclusive)
        float v_odd  = v_even + s_even;        // vals[2l+1]
        float mid = __shfl_sync(0xffffffff, v_odd, 12);   // vals[25]
        if (lane <= 24) {
            tab[2 * lane]     = make_float2(v_even - mid, s_even);
            tab[2 * lane + 1] = make_float2(v_odd  - mid, s_odd);
        }
        if (lane == 0) {
            float s = __ldg(scale + c);
            sh_s[0] = s * 25.0f;               // fold 1/GRID into the scale
            sh_s[1] = __fdividef(1.0f, s);
        }
    }
    __syncthreads();

    float s25   = sh_s[0];
    float inv_s = sh_s[1];

    // ---- evaluate + store, pairwise (frees v-regs as we go) ----------------
    {
        float xin0[4] = {v0.x, v0.y, v0.z, v0.w};
        float xin1[4] = {v1.x, v1.y, v1.z, v1.w};
        float r0[4], r1[4];
#pragma unroll
        for (int k = 0; k < 4; ++k) {
            float t  = xin0[k] * s25;                      // = xs / GRID
            float tc = fminf(fmaxf(t, TLO), THI);          // clamp in t-domain
            float fl = floorf(tc);                         // [-25, 24]
            float fr = t - fl;                             // frac from UNCLAMPED t
            int idx  = HALFI + (int)fl;                    // [0, 49]
            float2 p = tab[idx];                           // LDS.64 gather
            r0[k] = fmaf(fr, p.y, p.x) * inv_s;
        }
#pragma unroll
        for (int k = 0; k < 4; ++k) {
            float t  = xin1[k] * s25;
            float tc = fminf(fmaxf(t, TLO), THI);
            float fl = floorf(tc);
            float fr = t - fl;
            int idx  = HALFI + (int)fl;
            float2 p = tab[idx];
            r1[k] = fmaf(fr, p.y, p.x) * inv_s;
        }
        __stcs(out + base,           make_float4(r0[0], r0[1], r0[2], r0[3]));
        __stcs(out + base + THREADS, make_float4(r1[0], r1[1], r1[2], r1[3]));
    }
    {
        float xin0[4] = {v2.x, v2.y, v2.z, v2.w};
        float xin1[4] = {v3.x, v3.y, v3.z, v3.w};
        float r0[4], r1[4];
#pragma unroll
        for (int k = 0; k < 4; ++k) {
            float t  = xin0[k] * s25;
            float tc = fminf(fmaxf(t, TLO), THI);
            float fl = floorf(tc);
            float fr = t - fl;
            int idx  = HALFI + (int)fl;
            float2 p = tab[idx];
            r0[k] = fmaf(fr, p.y, p.x) * inv_s;
        }
#pragma unroll
        for (int k = 0; k < 4; ++k) {
            float t  = xin1[k] * s25;
            float tc = fminf(fmaxf(t, TLO), THI);
            float fl = floorf(tc);
            float fr = t - fl;
            int idx  = HALFI + (int)fl;
            float2 p = tab[idx];
            r1[k] = fmaf(fr, p.y, p.x) * inv_s;
        }
        __stcs(out + base + THREADS * 2, make_float4(r0[0], r0[1], r0[2], r0[3]));
        __stcs(out + base + THREADS * 3, make_float4(r1[0], r1[1], r1[2], r1[3]));
    }
}

extern "C" void kernel_launch(void* const* d_in, const int* in_sizes, int n_in,
                              void* d_out, int out_size) {
    const float* x     = (const float*)d_in[0];
    const float* coeff = (const float*)d_in[1];
    const float* scl   = (const float*)d_in[2];
    float* out = (float*)d_out;

    int n  = out_size;                 // 33554432
    int blocks = n / (BLOCK_V4 * 4);   // 32768
    spline_fused_kernel<<<blocks, THREADS>>>((const float4*)x, coeff, scl,
                                             (float4*)out);
}